// round 9
// baseline (speedup 1.0000x reference)
#include <cuda_runtime.h>
#include <cuda_fp16.h>

// EdgeConv: out[n] = A[n] - min_{src in in(n)} T[src]
//   T = feat @ W_theta              (fp16 -> halves gather L2 traffic)
//   A = feat @ (W_theta + W_phi) + (b_theta + b_phi)   (fp32)
// 4 launches: zero | combo(gemm+hist) | scan+scatter (fused, grid barrier) | gather

#define D 64
#define MAX_N 50000
#define MAX_E 800000
#define SCAN_BLK 1024
#define MAX_NB ((MAX_N + SCAN_BLK - 1) / SCAN_BLK)

__device__ __half2 g_Th[MAX_N * 32];
__device__ float   g_A[MAX_N * D];
__device__ int     g_deg[MAX_N];
__device__ int     g_offs[MAX_N + 1];
__device__ int     g_cursor[MAX_N];
__device__ int     g_esrc[MAX_E];
__device__ int     g_bsums[MAX_NB];    // aggregate+1, 0 = not ready
__device__ int     g_bar;              // grid barrier counter

// ---- f32x2 packed helpers --------------------------------------------------
__device__ __forceinline__ unsigned long long pack2(float x, float y) {
    unsigned long long r;
    asm("mov.b64 %0, {%1, %2};" : "=l"(r) : "f"(x), "f"(y));
    return r;
}
__device__ __forceinline__ void unpack2(unsigned long long v, float& x, float& y) {
    asm("mov.b64 {%0, %1}, %2;" : "=f"(x), "=f"(y) : "l"(v));
}
__device__ __forceinline__ void fma2(unsigned long long& d,
                                     unsigned long long a, unsigned long long b) {
    asm("fma.rn.f32x2 %0, %1, %2, %0;" : "+l"(d) : "l"(a), "l"(b));
}

// ---------------------------------------------------------------------------
// zero: deg[N], bsums[NB], barrier
// ---------------------------------------------------------------------------
__global__ void zero_kernel(int N, int NB)
{
    int i = blockIdx.x * blockDim.x + threadIdx.x;
    if (i < N) g_deg[i] = 0;
    else if (i < N + NB) g_bsums[i - N] = 0;
    if (i == 0) g_bar = 0;
}

// ---------------------------------------------------------------------------
// Combo: blocks [0, G_gemm) dual FFMA2 GEMM (64 rows each),
//        blocks [G_gemm, ...) degree histogram (4 edges/thread).
// ---------------------------------------------------------------------------
__global__ void __launch_bounds__(256) combo_kernel(
    const float* __restrict__ feat,
    const float* __restrict__ Wt, const float* __restrict__ bt,
    const float* __restrict__ Wp, const float* __restrict__ bp,
    const int* __restrict__ dst,
    int N, int E, int G_gemm)
{
    __shared__ float4 ws[D * 32];
    __shared__ float  f_s[64 * D];

    if (blockIdx.x >= G_gemm) {
        // ---- histogram: 4 edges per thread ----
        int base = (((blockIdx.x - G_gemm) * 256) + threadIdx.x) * 4;
        if (base + 3 < E) {
            int4 d4 = *(const int4*)(dst + base);
            if (d4.x >= 0 && d4.x < N) atomicAdd(&g_deg[d4.x], 1);
            if (d4.y >= 0 && d4.y < N) atomicAdd(&g_deg[d4.y], 1);
            if (d4.z >= 0 && d4.z < N) atomicAdd(&g_deg[d4.z], 1);
            if (d4.w >= 0 && d4.w < N) atomicAdd(&g_deg[d4.w], 1);
        } else {
            for (int i = base; i < E; i++) {
                int dn = dst[i];
                if (dn >= 0 && dn < N) atomicAdd(&g_deg[dn], 1);
            }
        }
        return;
    }

    // ---- GEMM ----
    int tid = threadIdx.x;
    int row0 = blockIdx.x * 64;

    {
        const float2* wt2 = (const float2*)Wt;
        const float2* wp2 = (const float2*)Wp;
        for (int i = tid; i < D * 32; i += 256) {
            float2 a = wt2[i];
            float2 b = wp2[i];
            ws[i] = make_float4(a.x, a.y, b.x, b.y);
        }
    }
    {
        float4* f4 = (float4*)f_s;
        const float4* feat4 = (const float4*)feat;
        for (int i = tid; i < 64 * (D / 4); i += 256) {
            int r = row0 + i / (D / 4);
            f4[i] = (r < N) ? feat4[(long)r * (D / 4) + (i & (D / 4 - 1))]
                            : make_float4(0.f, 0.f, 0.f, 0.f);
        }
    }
    __syncthreads();

    int dp = tid & 31;
    int rg = tid >> 5;

    unsigned long long at[8], ap[8];
#pragma unroll
    for (int r = 0; r < 8; r++) { at[r] = pack2(0.f, 0.f); ap[r] = pack2(0.f, 0.f); }

    const float2* f2p = (const float2*)f_s;

#pragma unroll
    for (int k = 0; k < D; k += 2) {
        float4 wa = ws[k * 32 + dp];
        float4 wb = ws[(k + 1) * 32 + dp];
        unsigned long long wt0 = pack2(wa.x, wa.y);
        unsigned long long wp0 = pack2(wa.z, wa.w);
        unsigned long long wt1 = pack2(wb.x, wb.y);
        unsigned long long wp1 = pack2(wb.z, wb.w);
#pragma unroll
        for (int r = 0; r < 8; r++) {
            float2 f = f2p[((rg * 8 + r) * D + k) >> 1];
            unsigned long long f0 = pack2(f.x, f.x);
            unsigned long long f1 = pack2(f.y, f.y);
            fma2(at[r], f0, wt0);
            fma2(ap[r], f0, wp0);
            fma2(at[r], f1, wt1);
            fma2(ap[r], f1, wp1);
        }
    }

    float bs0 = bt[2 * dp] + bp[2 * dp];
    float bs1 = bt[2 * dp + 1] + bp[2 * dp + 1];

    float2* A2 = (float2*)g_A;
#pragma unroll
    for (int r = 0; r < 8; r++) {
        int row = row0 + rg * 8 + r;
        if (row < N) {
            float tx, ty, px, py;
            unpack2(at[r], tx, ty);
            unpack2(ap[r], px, py);
            g_Th[row * 32 + dp] = __floats2half2_rn(tx, ty);
            A2[row * 32 + dp]   = make_float2(tx + px + bs0, ty + py + bs1);
        }
    }
}

// ---------------------------------------------------------------------------
// Fused scan + scatter. NB <= 49 blocks, all co-resident (148 SMs):
//   phase 1: decoupled single-pass exclusive scan -> offs, cursor
//   barrier: atomic arrive-and-poll across the grid
//   phase 2: scatter (4 edges/thread, 50k threads over 800k edges)
// ---------------------------------------------------------------------------
__global__ void __launch_bounds__(SCAN_BLK) scan_scatter_kernel(
    const int* __restrict__ src, const int* __restrict__ dst,
    int E, int N, int NB)
{
    __shared__ int warp_sums[32];
    __shared__ int s_agg;
    __shared__ int s_prefix;
    int tid  = threadIdx.x;
    int lane = tid & 31;
    int wid  = tid >> 5;
    int bid  = blockIdx.x;
    int i    = bid * SCAN_BLK + tid;

    int v = (i < N) ? g_deg[i] : 0;

    int incl = v;
#pragma unroll
    for (int off = 1; off < 32; off <<= 1) {
        int t = __shfl_up_sync(0xffffffffu, incl, off);
        if (lane >= off) incl += t;
    }
    if (lane == 31) warp_sums[wid] = incl;
    __syncthreads();

    if (wid == 0) {
        int ws_ = warp_sums[lane];
        int wincl = ws_;
#pragma unroll
        for (int off = 1; off < 32; off <<= 1) {
            int t = __shfl_up_sync(0xffffffffu, wincl, off);
            if (lane >= off) wincl += t;
        }
        warp_sums[lane] = wincl - ws_;
        if (lane == 31) {
            s_agg = wincl;
            atomicExch(&g_bsums[bid], wincl + 1);
        }
    }
    __syncthreads();

    if (wid == 0) {
        int sum = 0;
        for (int base = 0; base < bid; base += 32) {
            int j = base + lane;
            int val = 0;
            if (j < bid) {
                do { val = atomicAdd(&g_bsums[j], 0); } while (val == 0);
                val -= 1;
            }
            sum += val;
        }
#pragma unroll
        for (int off = 16; off >= 1; off >>= 1)
            sum += __shfl_xor_sync(0xffffffffu, sum, off);
        if (lane == 0) s_prefix = sum;
    }
    __syncthreads();

    int pre = s_prefix;
    if (i < N) {
        int o = incl - v + warp_sums[wid] + pre;
        g_offs[i]   = o;
        g_cursor[i] = o;
    }
    if (bid == NB - 1 && tid == 0) g_offs[N] = pre + s_agg;

    // ---- grid barrier ----
    __syncthreads();
    if (tid == 0) {
        __threadfence();
        atomicAdd(&g_bar, 1);
        while (atomicAdd(&g_bar, 0) < NB) { }
    }
    __syncthreads();

    // ---- scatter phase: 4 edges per thread per iteration ----
    int gtid   = bid * SCAN_BLK + tid;
    int stride = NB * SCAN_BLK;
    for (int base = gtid * 4; base < E; base += stride * 4) {
        if (base + 3 < E) {
            int4 s4 = *(const int4*)(src + base);
            int4 d4 = *(const int4*)(dst + base);
            if (d4.x >= 0 && d4.x < N && s4.x >= 0 && s4.x < N) {
                int p = atomicAdd(&g_cursor[d4.x], 1);
                if (p < MAX_E) g_esrc[p] = s4.x;
            }
            if (d4.y >= 0 && d4.y < N && s4.y >= 0 && s4.y < N) {
                int p = atomicAdd(&g_cursor[d4.y], 1);
                if (p < MAX_E) g_esrc[p] = s4.y;
            }
            if (d4.z >= 0 && d4.z < N && s4.z >= 0 && s4.z < N) {
                int p = atomicAdd(&g_cursor[d4.z], 1);
                if (p < MAX_E) g_esrc[p] = s4.z;
            }
            if (d4.w >= 0 && d4.w < N && s4.w >= 0 && s4.w < N) {
                int p = atomicAdd(&g_cursor[d4.w], 1);
                if (p < MAX_E) g_esrc[p] = s4.w;
            }
        } else {
            for (int j = base; j < E; j++) {
                int dn = dst[j];
                int sn = src[j];
                if (dn >= 0 && dn < N && sn >= 0 && sn < N) {
                    int p = atomicAdd(&g_cursor[dn], 1);
                    if (p < MAX_E) g_esrc[p] = sn;
                }
            }
        }
    }
}

// ---------------------------------------------------------------------------
// Gather: segment-min of fp16 T rows, out = A[n] - min.
// ---------------------------------------------------------------------------
__global__ void __launch_bounds__(256) gather_kernel(float* __restrict__ out, int N)
{
    int node = blockIdx.x * 8 + (threadIdx.x >> 5);
    int lane = threadIdx.x & 31;
    if (node >= N) return;

    int start = g_offs[node];
    int end   = g_offs[node + 1];

    __half2 m = __floats2half2_rn(65504.f, 65504.f);

#pragma unroll 4
    for (int j = start; j < end; j++) {
        int s = g_esrc[j];
        __half2 v = g_Th[s * 32 + lane];
        m = __hmin2(m, v);
    }

    float2 mf = __half22float2(m);
    const float2* __restrict__ A2 = (const float2*)g_A;
    float2 a = A2[node * 32 + lane];
    float2 o;
    o.x = a.x - mf.x;
    o.y = a.y - mf.y;
    ((float2*)out)[node * 32 + lane] = o;
}

// ---------------------------------------------------------------------------
extern "C" void kernel_launch(void* const* d_in, const int* in_sizes, int n_in,
                              void* d_out, int out_size)
{
    const float* feat = (const float*)d_in[0];
    const int*   src  = (const int*)d_in[1];
    const int*   dst  = (const int*)d_in[2];
    const float* Wt   = (const float*)d_in[3];
    const float* bt   = (const float*)d_in[4];
    const float* Wp   = (const float*)d_in[5];
    const float* bp   = (const float*)d_in[6];
    float*       out  = (float*)d_out;

    int N  = in_sizes[0] / D;
    int E  = in_sizes[1];
    int NB = (N + SCAN_BLK - 1) / SCAN_BLK;

    int G_gemm = (N + 63) / 64;
    int G_hist = ((E + 3) / 4 + 255) / 256;

    zero_kernel<<<(N + NB + 255) / 256, 256>>>(N, NB);
    combo_kernel<<<G_gemm + G_hist, 256>>>(feat, Wt, bt, Wp, bp, dst, N, E, G_gemm);
    scan_scatter_kernel<<<NB, SCAN_BLK>>>(src, dst, E, N, NB);
    gather_kernel<<<(N + 7) / 8, 256>>>(out, N);
}

// round 10
// speedup vs baseline: 1.1010x; 1.1010x over previous
#include <cuda_runtime.h>
#include <cuda_fp16.h>

// EdgeConv: out[n] = A[n] - min_{src in in(n)} T[src]
//   T = feat @ W_theta              (fp16 -> halves gather L2 traffic)
//   A = feat @ (W_theta + W_phi) + (b_theta + b_phi)   (fp32)
// 5 launches: zero | combo(gemm+hist) | scan(single-pass) | scatter | gather

#define D 64
#define MAX_N 50000
#define MAX_E 800000
#define SCAN_BLK 1024
#define MAX_NB ((MAX_N + SCAN_BLK - 1) / SCAN_BLK)

__device__ __half2 g_Th[MAX_N * 32];
__device__ float   g_A[MAX_N * D];
__device__ int     g_deg[MAX_N];
__device__ int     g_offs[MAX_N + 1];
__device__ int     g_cursor[MAX_N];
__device__ int     g_esrc[MAX_E];
__device__ int     g_bsums[MAX_NB];    // aggregate+1, 0 = not ready

// ---- f32x2 packed helpers --------------------------------------------------
__device__ __forceinline__ unsigned long long pack2(float x, float y) {
    unsigned long long r;
    asm("mov.b64 %0, {%1, %2};" : "=l"(r) : "f"(x), "f"(y));
    return r;
}
__device__ __forceinline__ void unpack2(unsigned long long v, float& x, float& y) {
    asm("mov.b64 {%0, %1}, %2;" : "=f"(x), "=f"(y) : "l"(v));
}
__device__ __forceinline__ void fma2(unsigned long long& d,
                                     unsigned long long a, unsigned long long b) {
    asm("fma.rn.f32x2 %0, %1, %2, %0;" : "+l"(d) : "l"(a), "l"(b));
}

// ---------------------------------------------------------------------------
// zero: deg[N] and bsums[NB]
// ---------------------------------------------------------------------------
__global__ void zero_kernel(int N, int NB)
{
    int i = blockIdx.x * blockDim.x + threadIdx.x;
    if (i < N) g_deg[i] = 0;
    else if (i < N + NB) g_bsums[i - N] = 0;
}

// ---------------------------------------------------------------------------
// Combo: blocks [0, G_gemm) dual FFMA2 GEMM (64 rows each),
//        blocks [G_gemm, ...) degree histogram (4 edges/thread).
// ---------------------------------------------------------------------------
__global__ void __launch_bounds__(256) combo_kernel(
    const float* __restrict__ feat,
    const float* __restrict__ Wt, const float* __restrict__ bt,
    const float* __restrict__ Wp, const float* __restrict__ bp,
    const int* __restrict__ dst,
    int N, int E, int G_gemm)
{
    __shared__ float4 ws[D * 32];
    __shared__ float  f_s[64 * D];

    if (blockIdx.x >= G_gemm) {
        // ---- histogram: 4 edges per thread ----
        int base = (((blockIdx.x - G_gemm) * 256) + threadIdx.x) * 4;
        if (base + 3 < E) {
            int4 d4 = *(const int4*)(dst + base);
            if (d4.x >= 0 && d4.x < N) atomicAdd(&g_deg[d4.x], 1);
            if (d4.y >= 0 && d4.y < N) atomicAdd(&g_deg[d4.y], 1);
            if (d4.z >= 0 && d4.z < N) atomicAdd(&g_deg[d4.z], 1);
            if (d4.w >= 0 && d4.w < N) atomicAdd(&g_deg[d4.w], 1);
        } else {
            for (int i = base; i < E; i++) {
                int dn = dst[i];
                if (dn >= 0 && dn < N) atomicAdd(&g_deg[dn], 1);
            }
        }
        return;
    }

    // ---- GEMM ----
    int tid = threadIdx.x;
    int row0 = blockIdx.x * 64;

    {
        const float2* wt2 = (const float2*)Wt;
        const float2* wp2 = (const float2*)Wp;
        for (int i = tid; i < D * 32; i += 256) {
            float2 a = wt2[i];
            float2 b = wp2[i];
            ws[i] = make_float4(a.x, a.y, b.x, b.y);
        }
    }
    {
        float4* f4 = (float4*)f_s;
        const float4* feat4 = (const float4*)feat;
        for (int i = tid; i < 64 * (D / 4); i += 256) {
            int r = row0 + i / (D / 4);
            f4[i] = (r < N) ? feat4[(long)r * (D / 4) + (i & (D / 4 - 1))]
                            : make_float4(0.f, 0.f, 0.f, 0.f);
        }
    }
    __syncthreads();

    int dp = tid & 31;
    int rg = tid >> 5;

    unsigned long long at[8], ap[8];
#pragma unroll
    for (int r = 0; r < 8; r++) { at[r] = pack2(0.f, 0.f); ap[r] = pack2(0.f, 0.f); }

    const float2* f2p = (const float2*)f_s;

#pragma unroll
    for (int k = 0; k < D; k += 2) {
        float4 wa = ws[k * 32 + dp];
        float4 wb = ws[(k + 1) * 32 + dp];
        unsigned long long wt0 = pack2(wa.x, wa.y);
        unsigned long long wp0 = pack2(wa.z, wa.w);
        unsigned long long wt1 = pack2(wb.x, wb.y);
        unsigned long long wp1 = pack2(wb.z, wb.w);
#pragma unroll
        for (int r = 0; r < 8; r++) {
            float2 f = f2p[((rg * 8 + r) * D + k) >> 1];
            unsigned long long f0 = pack2(f.x, f.x);
            unsigned long long f1 = pack2(f.y, f.y);
            fma2(at[r], f0, wt0);
            fma2(ap[r], f0, wp0);
            fma2(at[r], f1, wt1);
            fma2(ap[r], f1, wp1);
        }
    }

    float bs0 = bt[2 * dp] + bp[2 * dp];
    float bs1 = bt[2 * dp + 1] + bp[2 * dp + 1];

    float2* A2 = (float2*)g_A;
#pragma unroll
    for (int r = 0; r < 8; r++) {
        int row = row0 + rg * 8 + r;
        if (row < N) {
            float tx, ty, px, py;
            unpack2(at[r], tx, ty);
            unpack2(ap[r], px, py);
            g_Th[row * 32 + dp] = __floats2half2_rn(tx, ty);
            A2[row * 32 + dp]   = make_float2(tx + px + bs0, ty + py + bs1);
        }
    }
}

// ---------------------------------------------------------------------------
// Single-pass decoupled scan (NB <= 49 co-resident blocks).
// ---------------------------------------------------------------------------
__global__ void __launch_bounds__(SCAN_BLK) scan_kernel(int N, int NB)
{
    __shared__ int warp_sums[32];
    __shared__ int s_agg;
    __shared__ int s_prefix;
    int tid  = threadIdx.x;
    int lane = tid & 31;
    int wid  = tid >> 5;
    int bid  = blockIdx.x;
    int i    = bid * SCAN_BLK + tid;

    int v = (i < N) ? g_deg[i] : 0;

    int incl = v;
#pragma unroll
    for (int off = 1; off < 32; off <<= 1) {
        int t = __shfl_up_sync(0xffffffffu, incl, off);
        if (lane >= off) incl += t;
    }
    if (lane == 31) warp_sums[wid] = incl;
    __syncthreads();

    if (wid == 0) {
        int ws_ = warp_sums[lane];
        int wincl = ws_;
#pragma unroll
        for (int off = 1; off < 32; off <<= 1) {
            int t = __shfl_up_sync(0xffffffffu, wincl, off);
            if (lane >= off) wincl += t;
        }
        warp_sums[lane] = wincl - ws_;
        if (lane == 31) {
            s_agg = wincl;
            atomicExch(&g_bsums[bid], wincl + 1);
        }
    }
    __syncthreads();

    if (wid == 0) {
        int sum = 0;
        for (int base = 0; base < bid; base += 32) {
            int j = base + lane;
            int val = 0;
            if (j < bid) {
                do { val = atomicAdd(&g_bsums[j], 0); } while (val == 0);
                val -= 1;
            }
            sum += val;
        }
#pragma unroll
        for (int off = 16; off >= 1; off >>= 1)
            sum += __shfl_xor_sync(0xffffffffu, sum, off);
        if (lane == 0) s_prefix = sum;
    }
    __syncthreads();

    int pre = s_prefix;
    if (i < N) {
        int o = incl - v + warp_sums[wid] + pre;
        g_offs[i]   = o;
        g_cursor[i] = o;
    }
    if (bid == NB - 1 && tid == 0) g_offs[N] = pre + s_agg;
}

// ---------------------------------------------------------------------------
// Scatter: 4 edges/thread (int4), full thread count -> high cross-thread MLP.
// ---------------------------------------------------------------------------
__global__ void scatter_kernel(const int* __restrict__ src,
                               const int* __restrict__ dst, int E, int N)
{
    int base = (blockIdx.x * blockDim.x + threadIdx.x) * 4;
    if (base + 3 < E) {
        int4 s4 = *(const int4*)(src + base);
        int4 d4 = *(const int4*)(dst + base);
        if (d4.x >= 0 && d4.x < N && s4.x >= 0 && s4.x < N) {
            int p = atomicAdd(&g_cursor[d4.x], 1);
            if (p < MAX_E) g_esrc[p] = s4.x;
        }
        if (d4.y >= 0 && d4.y < N && s4.y >= 0 && s4.y < N) {
            int p = atomicAdd(&g_cursor[d4.y], 1);
            if (p < MAX_E) g_esrc[p] = s4.y;
        }
        if (d4.z >= 0 && d4.z < N && s4.z >= 0 && s4.z < N) {
            int p = atomicAdd(&g_cursor[d4.z], 1);
            if (p < MAX_E) g_esrc[p] = s4.z;
        }
        if (d4.w >= 0 && d4.w < N && s4.w >= 0 && s4.w < N) {
            int p = atomicAdd(&g_cursor[d4.w], 1);
            if (p < MAX_E) g_esrc[p] = s4.w;
        }
    } else {
        for (int i = base; i < E; i++) {
            int dn = dst[i];
            int sn = src[i];
            if (dn >= 0 && dn < N && sn >= 0 && sn < N) {
                int p = atomicAdd(&g_cursor[dn], 1);
                if (p < MAX_E) g_esrc[p] = sn;
            }
        }
    }
}

// ---------------------------------------------------------------------------
// Gather: segment-min of fp16 T rows. One warp/node. Edge indices are loaded
// 32-at-a-time coalesced into registers, shfl-broadcast, and the min body is
// unrolled 4-deep with independent accumulators -> 4 in-flight T-row loads.
// ---------------------------------------------------------------------------
__global__ void __launch_bounds__(256) gather_kernel(float* __restrict__ out, int N)
{
    int node = blockIdx.x * 8 + (threadIdx.x >> 5);
    int lane = threadIdx.x & 31;
    if (node >= N) return;

    int start = g_offs[node];
    int end   = g_offs[node + 1];

    const __half2* __restrict__ Th = g_Th;
    __half2 m0 = __floats2half2_rn(65504.f, 65504.f);
    __half2 m1 = m0, m2 = m0, m3 = m0;

    for (int base = start; base < end; base += 32) {
        int cnt  = min(32, end - base);
        int sidx = (base + lane < end) ? g_esrc[base + lane] : 0;

        int k = 0;
        for (; k + 4 <= cnt; k += 4) {
            int s0 = __shfl_sync(0xffffffffu, sidx, k);
            int s1 = __shfl_sync(0xffffffffu, sidx, k + 1);
            int s2 = __shfl_sync(0xffffffffu, sidx, k + 2);
            int s3 = __shfl_sync(0xffffffffu, sidx, k + 3);
            __half2 v0 = Th[s0 * 32 + lane];
            __half2 v1 = Th[s1 * 32 + lane];
            __half2 v2 = Th[s2 * 32 + lane];
            __half2 v3 = Th[s3 * 32 + lane];
            m0 = __hmin2(m0, v0);
            m1 = __hmin2(m1, v1);
            m2 = __hmin2(m2, v2);
            m3 = __hmin2(m3, v3);
        }
        for (; k < cnt; k++) {
            int s = __shfl_sync(0xffffffffu, sidx, k);
            m0 = __hmin2(m0, Th[s * 32 + lane]);
        }
    }

    m0 = __hmin2(__hmin2(m0, m1), __hmin2(m2, m3));

    float2 mf = __half22float2(m0);
    const float2* __restrict__ A2 = (const float2*)g_A;
    float2 a = A2[node * 32 + lane];
    float2 o;
    o.x = a.x - mf.x;
    o.y = a.y - mf.y;
    ((float2*)out)[node * 32 + lane] = o;
}

// ---------------------------------------------------------------------------
extern "C" void kernel_launch(void* const* d_in, const int* in_sizes, int n_in,
                              void* d_out, int out_size)
{
    const float* feat = (const float*)d_in[0];
    const int*   src  = (const int*)d_in[1];
    const int*   dst  = (const int*)d_in[2];
    const float* Wt   = (const float*)d_in[3];
    const float* bt   = (const float*)d_in[4];
    const float* Wp   = (const float*)d_in[5];
    const float* bp   = (const float*)d_in[6];
    float*       out  = (float*)d_out;

    int N  = in_sizes[0] / D;
    int E  = in_sizes[1];
    int NB = (N + SCAN_BLK - 1) / SCAN_BLK;

    int G_gemm = (N + 63) / 64;
    int G_hist = ((E + 3) / 4 + 255) / 256;

    zero_kernel<<<(N + NB + 255) / 256, 256>>>(N, NB);
    combo_kernel<<<G_gemm + G_hist, 256>>>(feat, Wt, bt, Wp, bp, dst, N, E, G_gemm);
    scan_kernel<<<NB, SCAN_BLK>>>(N, NB);
    scatter_kernel<<<((E + 3) / 4 + 255) / 256, 256>>>(src, dst, E, N);
    gather_kernel<<<(N + 7) / 8, 256>>>(out, N);
}

// round 11
// speedup vs baseline: 1.1445x; 1.0395x over previous
#include <cuda_runtime.h>
#include <cuda_fp16.h>

// EdgeConv: out[n] = A[n] - min_{src in in(n)} T[src]
//   T = feat @ W_theta              (fp16 -> halves gather L2 traffic)
//   A = feat @ (W_theta + W_phi) + (b_theta + b_phi)   (fp32)
// 5 launches: zero | combo(gemm + hist-with-rank) | scan | scatter(atomic-free) | gather
// hist's atomicAdd return value IS the edge's rank within its dst segment, so
// scatter needs no atomics: p = offs[dst] + rank.

#define D 64
#define MAX_N 50000
#define MAX_E 800000
#define SCAN_BLK 1024
#define MAX_NB ((MAX_N + SCAN_BLK - 1) / SCAN_BLK)

__device__ __half2 g_Th[MAX_N * 32];
__device__ float   g_A[MAX_N * D];
__device__ int     g_deg[MAX_N];
__device__ int     g_offs[MAX_N + 1];
__device__ int     g_esrc[MAX_E];
__device__ int     g_erank[MAX_E];
__device__ int     g_bsums[MAX_NB];    // aggregate+1, 0 = not ready

// ---- f32x2 packed helpers --------------------------------------------------
__device__ __forceinline__ unsigned long long pack2(float x, float y) {
    unsigned long long r;
    asm("mov.b64 %0, {%1, %2};" : "=l"(r) : "f"(x), "f"(y));
    return r;
}
__device__ __forceinline__ void unpack2(unsigned long long v, float& x, float& y) {
    asm("mov.b64 {%0, %1}, %2;" : "=f"(x), "=f"(y) : "l"(v));
}
__device__ __forceinline__ void fma2(unsigned long long& d,
                                     unsigned long long a, unsigned long long b) {
    asm("fma.rn.f32x2 %0, %1, %2, %0;" : "+l"(d) : "l"(a), "l"(b));
}

// ---------------------------------------------------------------------------
// zero: deg[N] and bsums[NB]
// ---------------------------------------------------------------------------
__global__ void zero_kernel(int N, int NB)
{
    int i = blockIdx.x * blockDim.x + threadIdx.x;
    if (i < N) g_deg[i] = 0;
    else if (i < N + NB) g_bsums[i - N] = 0;
}

// ---------------------------------------------------------------------------
// Combo: blocks [0, G_gemm) dual FFMA2 GEMM (64 rows each),
//        blocks [G_gemm, ...) histogram + rank recording (4 edges/thread).
// ---------------------------------------------------------------------------
__global__ void __launch_bounds__(256) combo_kernel(
    const float* __restrict__ feat,
    const float* __restrict__ Wt, const float* __restrict__ bt,
    const float* __restrict__ Wp, const float* __restrict__ bp,
    const int* __restrict__ dst,
    int N, int E, int G_gemm)
{
    __shared__ float4 ws[D * 32];
    __shared__ float  f_s[64 * D];

    if (blockIdx.x >= G_gemm) {
        // ---- histogram + rank: 4 edges per thread ----
        int base = (((blockIdx.x - G_gemm) * 256) + threadIdx.x) * 4;
        if (base + 3 < E) {
            int4 d4 = *(const int4*)(dst + base);
            int4 r4 = make_int4(0, 0, 0, 0);
            if (d4.x >= 0 && d4.x < N) r4.x = atomicAdd(&g_deg[d4.x], 1);
            if (d4.y >= 0 && d4.y < N) r4.y = atomicAdd(&g_deg[d4.y], 1);
            if (d4.z >= 0 && d4.z < N) r4.z = atomicAdd(&g_deg[d4.z], 1);
            if (d4.w >= 0 && d4.w < N) r4.w = atomicAdd(&g_deg[d4.w], 1);
            *(int4*)(g_erank + base) = r4;
        } else {
            for (int i = base; i < E; i++) {
                int dn = dst[i];
                g_erank[i] = (dn >= 0 && dn < N) ? atomicAdd(&g_deg[dn], 1) : 0;
            }
        }
        return;
    }

    // ---- GEMM ----
    int tid = threadIdx.x;
    int row0 = blockIdx.x * 64;

    {
        const float2* wt2 = (const float2*)Wt;
        const float2* wp2 = (const float2*)Wp;
        for (int i = tid; i < D * 32; i += 256) {
            float2 a = wt2[i];
            float2 b = wp2[i];
            ws[i] = make_float4(a.x, a.y, b.x, b.y);
        }
    }
    {
        float4* f4 = (float4*)f_s;
        const float4* feat4 = (const float4*)feat;
        for (int i = tid; i < 64 * (D / 4); i += 256) {
            int r = row0 + i / (D / 4);
            f4[i] = (r < N) ? feat4[(long)r * (D / 4) + (i & (D / 4 - 1))]
                            : make_float4(0.f, 0.f, 0.f, 0.f);
        }
    }
    __syncthreads();

    int dp = tid & 31;
    int rg = tid >> 5;

    unsigned long long at[8], ap[8];
#pragma unroll
    for (int r = 0; r < 8; r++) { at[r] = pack2(0.f, 0.f); ap[r] = pack2(0.f, 0.f); }

    const float2* f2p = (const float2*)f_s;

#pragma unroll
    for (int k = 0; k < D; k += 2) {
        float4 wa = ws[k * 32 + dp];
        float4 wb = ws[(k + 1) * 32 + dp];
        unsigned long long wt0 = pack2(wa.x, wa.y);
        unsigned long long wp0 = pack2(wa.z, wa.w);
        unsigned long long wt1 = pack2(wb.x, wb.y);
        unsigned long long wp1 = pack2(wb.z, wb.w);
#pragma unroll
        for (int r = 0; r < 8; r++) {
            float2 f = f2p[((rg * 8 + r) * D + k) >> 1];
            unsigned long long f0 = pack2(f.x, f.x);
            unsigned long long f1 = pack2(f.y, f.y);
            fma2(at[r], f0, wt0);
            fma2(ap[r], f0, wp0);
            fma2(at[r], f1, wt1);
            fma2(ap[r], f1, wp1);
        }
    }

    float bs0 = bt[2 * dp] + bp[2 * dp];
    float bs1 = bt[2 * dp + 1] + bp[2 * dp + 1];

    float2* A2 = (float2*)g_A;
#pragma unroll
    for (int r = 0; r < 8; r++) {
        int row = row0 + rg * 8 + r;
        if (row < N) {
            float tx, ty, px, py;
            unpack2(at[r], tx, ty);
            unpack2(ap[r], px, py);
            g_Th[row * 32 + dp] = __floats2half2_rn(tx, ty);
            A2[row * 32 + dp]   = make_float2(tx + px + bs0, ty + py + bs1);
        }
    }
}

// ---------------------------------------------------------------------------
// Single-pass decoupled scan (NB <= 49 co-resident blocks). offs only.
// ---------------------------------------------------------------------------
__global__ void __launch_bounds__(SCAN_BLK) scan_kernel(int N, int NB)
{
    __shared__ int warp_sums[32];
    __shared__ int s_agg;
    __shared__ int s_prefix;
    int tid  = threadIdx.x;
    int lane = tid & 31;
    int wid  = tid >> 5;
    int bid  = blockIdx.x;
    int i    = bid * SCAN_BLK + tid;

    int v = (i < N) ? g_deg[i] : 0;

    int incl = v;
#pragma unroll
    for (int off = 1; off < 32; off <<= 1) {
        int t = __shfl_up_sync(0xffffffffu, incl, off);
        if (lane >= off) incl += t;
    }
    if (lane == 31) warp_sums[wid] = incl;
    __syncthreads();

    if (wid == 0) {
        int ws_ = warp_sums[lane];
        int wincl = ws_;
#pragma unroll
        for (int off = 1; off < 32; off <<= 1) {
            int t = __shfl_up_sync(0xffffffffu, wincl, off);
            if (lane >= off) wincl += t;
        }
        warp_sums[lane] = wincl - ws_;
        if (lane == 31) {
            s_agg = wincl;
            atomicExch(&g_bsums[bid], wincl + 1);
        }
    }
    __syncthreads();

    if (wid == 0) {
        int sum = 0;
        for (int base = 0; base < bid; base += 32) {
            int j = base + lane;
            int val = 0;
            if (j < bid) {
                do { val = atomicAdd(&g_bsums[j], 0); } while (val == 0);
                val -= 1;
            }
            sum += val;
        }
#pragma unroll
        for (int off = 16; off >= 1; off >>= 1)
            sum += __shfl_xor_sync(0xffffffffu, sum, off);
        if (lane == 0) s_prefix = sum;
    }
    __syncthreads();

    int pre = s_prefix;
    if (i < N) g_offs[i] = incl - v + warp_sums[wid] + pre;
    if (bid == NB - 1 && tid == 0) g_offs[N] = pre + s_agg;
}

// ---------------------------------------------------------------------------
// Scatter, atomic-free: p = offs[dst] + rank. 4 edges/thread, int4 loads,
// 4 independent load->store chains per thread.
// ---------------------------------------------------------------------------
__global__ void scatter_kernel(const int* __restrict__ src,
                               const int* __restrict__ dst, int E, int N)
{
    int base = (blockIdx.x * blockDim.x + threadIdx.x) * 4;
    if (base + 3 < E) {
        int4 s4 = *(const int4*)(src + base);
        int4 d4 = *(const int4*)(dst + base);
        int4 r4 = *(const int4*)(g_erank + base);
        if (d4.x >= 0 && d4.x < N && s4.x >= 0 && s4.x < N)
            g_esrc[g_offs[d4.x] + r4.x] = s4.x;
        if (d4.y >= 0 && d4.y < N && s4.y >= 0 && s4.y < N)
            g_esrc[g_offs[d4.y] + r4.y] = s4.y;
        if (d4.z >= 0 && d4.z < N && s4.z >= 0 && s4.z < N)
            g_esrc[g_offs[d4.z] + r4.z] = s4.z;
        if (d4.w >= 0 && d4.w < N && s4.w >= 0 && s4.w < N)
            g_esrc[g_offs[d4.w] + r4.w] = s4.w;
    } else {
        for (int i = base; i < E; i++) {
            int dn = dst[i];
            int sn = src[i];
            if (dn >= 0 && dn < N && sn >= 0 && sn < N)
                g_esrc[g_offs[dn] + g_erank[i]] = sn;
        }
    }
}

// ---------------------------------------------------------------------------
// Gather: segment-min of fp16 T rows. One warp/node, coalesced index batch,
// 4-deep unrolled body with independent accumulators.
// ---------------------------------------------------------------------------
__global__ void __launch_bounds__(256) gather_kernel(float* __restrict__ out, int N)
{
    int node = blockIdx.x * 8 + (threadIdx.x >> 5);
    int lane = threadIdx.x & 31;
    if (node >= N) return;

    int start = g_offs[node];
    int end   = g_offs[node + 1];

    const __half2* __restrict__ Th = g_Th;
    __half2 m0 = __floats2half2_rn(65504.f, 65504.f);
    __half2 m1 = m0, m2 = m0, m3 = m0;

    for (int base = start; base < end; base += 32) {
        int cnt  = min(32, end - base);
        int sidx = (base + lane < end) ? g_esrc[base + lane] : 0;

        int k = 0;
        for (; k + 4 <= cnt; k += 4) {
            int s0 = __shfl_sync(0xffffffffu, sidx, k);
            int s1 = __shfl_sync(0xffffffffu, sidx, k + 1);
            int s2 = __shfl_sync(0xffffffffu, sidx, k + 2);
            int s3 = __shfl_sync(0xffffffffu, sidx, k + 3);
            __half2 v0 = Th[s0 * 32 + lane];
            __half2 v1 = Th[s1 * 32 + lane];
            __half2 v2 = Th[s2 * 32 + lane];
            __half2 v3 = Th[s3 * 32 + lane];
            m0 = __hmin2(m0, v0);
            m1 = __hmin2(m1, v1);
            m2 = __hmin2(m2, v2);
            m3 = __hmin2(m3, v3);
        }
        for (; k < cnt; k++) {
            int s = __shfl_sync(0xffffffffu, sidx, k);
            m0 = __hmin2(m0, Th[s * 32 + lane]);
        }
    }

    m0 = __hmin2(__hmin2(m0, m1), __hmin2(m2, m3));

    float2 mf = __half22float2(m0);
    const float2* __restrict__ A2 = (const float2*)g_A;
    float2 a = A2[node * 32 + lane];
    float2 o;
    o.x = a.x - mf.x;
    o.y = a.y - mf.y;
    ((float2*)out)[node * 32 + lane] = o;
}

// ---------------------------------------------------------------------------
extern "C" void kernel_launch(void* const* d_in, const int* in_sizes, int n_in,
                              void* d_out, int out_size)
{
    const float* feat = (const float*)d_in[0];
    const int*   src  = (const int*)d_in[1];
    const int*   dst  = (const int*)d_in[2];
    const float* Wt   = (const float*)d_in[3];
    const float* bt   = (const float*)d_in[4];
    const float* Wp   = (const float*)d_in[5];
    const float* bp   = (const float*)d_in[6];
    float*       out  = (float*)d_out;

    int N  = in_sizes[0] / D;
    int E  = in_sizes[1];
    int NB = (N + SCAN_BLK - 1) / SCAN_BLK;

    int G_gemm = (N + 63) / 64;
    int G_hist = ((E + 3) / 4 + 255) / 256;

    zero_kernel<<<(N + NB + 255) / 256, 256>>>(N, NB);
    combo_kernel<<<G_gemm + G_hist, 256>>>(feat, Wt, bt, Wp, bp, dst, N, E, G_gemm);
    scan_kernel<<<NB, SCAN_BLK>>>(N, NB);
    scatter_kernel<<<((E + 3) / 4 + 255) / 256, 256>>>(src, dst, E, N);
    gather_kernel<<<(N + 7) / 8, 256>>>(out, N);
}